// round 2
// baseline (speedup 1.0000x reference)
#include <cuda_runtime.h>

// ---------------------------------------------------------------------------
// TemporalFootAndBall detection post-process, GB300 (sm_103a)
//
// player map: B=64, C=2, H=68,  W=120, downscale=16, with bbox regression
// ball map:   B=64, C=2, H=272, W=480, downscale=4,  fixed 20x20 boxes
// out: (64, 200, 5) f32  [player top-100 dets ++ ball top-100 dets]
//
// All ranking / NMS comparisons are done on the float32 conf values computed
// bit-identically to XLA's softmax (libdevice __nv_expf + IEEE div), so tie
// structure matches the reference exactly. conf > 0, so raw conf bits order
// identically to float compare -> used directly as u32 radix/sort keys.
// ---------------------------------------------------------------------------

#define B_DIM   64
#define P_H     68
#define P_W     120
#define P_HW    (P_H * P_W)       // 8160
#define B_H     272
#define B_W     480
#define B_HW    (B_H * B_W)       // 130560
#define MAXDET  100

// Static scratch (allocation-free). Capacity = hw per row: local-maxima count
// can never exceed hw, so no overflow is possible.
__device__ unsigned long long g_cand_p[B_DIM * P_HW];
__device__ unsigned long long g_cand_b[(size_t)B_DIM * B_HW];
__device__ int g_cnt[2 * B_DIM];   // [0,64): player rows, [64,128): ball rows

__global__ void zero_cnt_kernel() {
    g_cnt[threadIdx.x] = 0;
}

// Bit-exact replication of libdevice __nv_expf (what XLA's f32 exp lowers to)
// for |a| < 104 (always true here: a = min(x0,x1)-max(x0,x1) in ~[-15, 0]).
// Immune to --use_fast_math (fmaf / exact mul by 2^i only).
__device__ __forceinline__ float xla_expf(float a) {
    float j = fmaf(a, 0x1.715476p+0f, 0x1.8p+23f) - 0x1.8p+23f;  // rint(a*log2e)
    float f = fmaf(j, -0x1.62e400p-1f, a);    // a - j*ln2_hi
    f = fmaf(j, -0x1.7f7d1cp-20f, f);         //   - j*ln2_lo
    const int i = (int)j;
    float r = 0x1.694000p-10f;
    r = fmaf(r, f, 0x1.125edcp-7f);
    r = fmaf(r, f, 0x1.555b5ap-5f);
    r = fmaf(r, f, 0x1.555450p-3f);
    r = fmaf(r, f, 0x1.fffff6p-2f);
    r = fmaf(r, f, 1.0f);
    r = fmaf(r, f, 1.0f);
    // exact scale by 2^i  (i in [-151, 0] here; our args give i >= -25)
    return r * __uint_as_float((unsigned)(127 + i) << 23);
}

// softmax([x0,x1]) channel 1, computed exactly as jax.nn.softmax does in f32:
// m = max(x0,x1); e_k = exp(x_k - m); conf = e1 / (e0 + e1).
__device__ __forceinline__ float softmax1(float x0, float x1) {
    const float m = fmaxf(x0, x1);
    const float e = xla_expf(fminf(x0, x1) - m);  // == exp of the smaller arg
    const float e1 = (x1 >= x0) ? 1.0f : e;      // exp(0) == 1 exactly
    return __fdiv_rn(e1, 1.0f + e);              // IEEE div, fast-math-proof
}

// ---------------------------------------------------------------------------
// Fused softmax + 3x3 NMS (SAME padding, -inf init) -> per-row candidate list.
// Tile 32x8 with 1-pixel halo in shared memory. One global atomic per CTA.
// ---------------------------------------------------------------------------
template <int H, int W, bool IS_PLAYER>
__global__ __launch_bounds__(256) void nms_kernel(const float* __restrict__ fm) {
    constexpr int TX = 32, TY = 8;
    __shared__ float tile[TY + 2][TX + 2];
    __shared__ int s_cnt, s_base;

    const int b  = blockIdx.z;
    const int x0 = blockIdx.x * TX;
    const int y0 = blockIdx.y * TY;
    const float* f0 = fm + (size_t)b * 2 * H * W;
    const float* f1 = f0 + H * W;
    const int tid = threadIdx.y * TX + threadIdx.x;

    if (tid == 0) s_cnt = 0;

    // Load halo tile of conf (out of range -> -inf, matching SAME/-inf pool).
    for (int i = tid; i < (TY + 2) * (TX + 2); i += TX * TY) {
        const int ly = i / (TX + 2), lx = i % (TX + 2);
        const int gy = y0 + ly - 1, gx = x0 + lx - 1;
        float c;
        if (gy >= 0 && gy < H && gx >= 0 && gx < W) {
            const int o = gy * W + gx;
            c = softmax1(f0[o], f1[o]);
        } else {
            c = __int_as_float(0xFF800000);  // -inf
        }
        tile[ly][lx] = c;
    }
    __syncthreads();

    const int gx = x0 + threadIdx.x;
    const int gy = y0 + threadIdx.y;
    bool kept = false;
    int my = 0;
    unsigned cbits = 0;
    if (gx < W && gy < H) {
        const int ly = threadIdx.y + 1, lx = threadIdx.x + 1;
        const float v = tile[ly][lx];
        float p = v;
        p = fmaxf(p, tile[ly - 1][lx - 1]);
        p = fmaxf(p, tile[ly - 1][lx    ]);
        p = fmaxf(p, tile[ly - 1][lx + 1]);
        p = fmaxf(p, tile[ly    ][lx - 1]);
        p = fmaxf(p, tile[ly    ][lx + 1]);
        p = fmaxf(p, tile[ly + 1][lx - 1]);
        p = fmaxf(p, tile[ly + 1][lx    ]);
        p = fmaxf(p, tile[ly + 1][lx + 1]);
        if (v == p) {  // local max (ties kept, matching x == pooled)
            kept = true;
            cbits = __float_as_uint(v);  // conf > 0 -> bits order == float order
            my = atomicAdd(&s_cnt, 1);
        }
    }
    __syncthreads();
    if (tid == 0)
        s_base = atomicAdd(&g_cnt[(IS_PLAYER ? 0 : B_DIM) + b], s_cnt);
    __syncthreads();
    if (kept) {
        unsigned long long* cand =
            (IS_PLAYER ? g_cand_p : g_cand_b) + (size_t)b * (H * W);
        cand[s_base + my] =
            ((unsigned long long)cbits << 32) | (unsigned)(gy * W + gx);
    }
}

// ---------------------------------------------------------------------------
// Per-row top-100: MSB-first radix descent -> collect -> bitonic sort -> emit.
// blockIdx.x in [0,64): player row; [64,128): ball row.
// ---------------------------------------------------------------------------
__global__ __launch_bounds__(1024) void select_kernel(
    const float* __restrict__ pbb, float* __restrict__ out) {
    constexpr int CAP = 4096;
    __shared__ unsigned hist[256];
    __shared__ unsigned long long buf[CAP];
    __shared__ unsigned sh_above, sh_prefix, sh_set, sh_cnt;

    const int blk = blockIdx.x;
    const bool is_player = (blk < B_DIM);
    const int b = is_player ? blk : blk - B_DIM;
    const int n = g_cnt[blk];
    const unsigned long long* cand =
        is_player ? (g_cand_p + (size_t)b * P_HW)
                  : (g_cand_b + (size_t)b * B_HW);
    const int tid = threadIdx.x;

    // Radix descent: find threshold T with 100 <= |{score >= T}| <= CAP.
    unsigned prefix = 0, above = 0, thresh = 0;
    for (int s = 24;; s -= 8) {
        for (int i = tid; i < 256; i += blockDim.x) hist[i] = 0;
        __syncthreads();
        const unsigned mask = (s == 24) ? 0u : (0xFFFFFFFFu << (s + 8));
        for (int i = tid; i < n; i += blockDim.x) {
            const unsigned sc = (unsigned)(cand[i] >> 32);
            if ((sc & mask) == prefix) atomicAdd(&hist[(sc >> s) & 255u], 1u);
        }
        __syncthreads();
        if (tid == 0) {
            unsigned acc = above, setc = 0;
            int bin = 0;
            for (int bb = 255; bb >= 0; --bb) {
                if (acc + hist[bb] >= (unsigned)MAXDET || bb == 0) {
                    bin = bb;
                    setc = acc + hist[bb];
                    break;
                }
                acc += hist[bb];
            }
            sh_above  = acc;
            sh_prefix = prefix | ((unsigned)bin << s);
            sh_set    = setc;
        }
        __syncthreads();
        above  = sh_above;
        prefix = sh_prefix;
        if (sh_set <= (unsigned)CAP || s == 0) {
            thresh = prefix;
            break;
        }
    }

    // Collect all candidates with score >= thresh; key = (score << 32) | ~idx
    // so descending-key order == (score desc, idx asc) == lax.top_k order.
    if (tid == 0) sh_cnt = 0;
    __syncthreads();
    for (int i = tid; i < n; i += blockDim.x) {
        const unsigned long long cv = cand[i];
        const unsigned sc = (unsigned)(cv >> 32);
        if (sc >= thresh) {
            const unsigned pos = atomicAdd(&sh_cnt, 1u);
            if (pos < (unsigned)CAP)
                buf[pos] = (cv & 0xFFFFFFFF00000000ull) |
                           (unsigned)(~(unsigned)cv);
        }
    }
    __syncthreads();

    const int m = (int)min(sh_cnt, (unsigned)CAP);
    int N = 128;
    while (N < m) N <<= 1;
    for (int i = m + tid; i < N; i += blockDim.x) buf[i] = 0ull;
    __syncthreads();

    // Bitonic sort, descending.
    for (int k = 2; k <= N; k <<= 1) {
        for (int j = k >> 1; j > 0; j >>= 1) {
            for (int i = tid; i < N; i += blockDim.x) {
                const int ixj = i ^ j;
                if (ixj > i) {
                    const unsigned long long a = buf[i], c = buf[ixj];
                    const bool up = ((i & k) == 0);
                    if (up ? (a < c) : (a > c)) {
                        buf[i]   = c;
                        buf[ixj] = a;
                    }
                }
            }
            __syncthreads();
        }
    }

    // Emit top-100.
    if (tid < MAXDET) {
        float o0, o1, o2, o3, o4;
        if (tid < m) {
            const unsigned long long key = buf[tid];
            const unsigned usc = (unsigned)(key >> 32);
            const unsigned idx = ~(unsigned)key;
            const float conf = __uint_as_float(usc);  // bit-exact softmax ch1
            if (is_player) {
                const int x = (int)idx % P_W;
                const int y = (int)idx / P_W;
                const float xc = (float)x * 16.0f + 7.5f;
                const float yc = (float)y * 16.0f + 7.5f;
                const float* bp = pbb + (size_t)b * 4 * P_HW + idx;
                const float t0 = bp[0 * P_HW] * 1920.0f;  // W*ds
                const float t1 = bp[1 * P_HW] * 1088.0f;  // H*ds
                const float t2 = bp[2 * P_HW] * 1920.0f;
                const float t3 = bp[3 * P_HW] * 1088.0f;
                const float bx = xc + t0, by = yc + t1;
                o0 = bx - 0.5f * t2;
                o1 = by - 0.5f * t3;
                o2 = bx + 0.5f * t2;
                o3 = by + 0.5f * t3;
                o4 = conf;
            } else {
                const int x = (int)idx % B_W;
                const int y = (int)idx / B_W;
                const float xc = (float)x * 4.0f + 1.5f;
                const float yc = (float)y * 4.0f + 1.5f;
                o0 = xc - 10.0f;
                o1 = yc - 10.0f;
                o2 = xc + 10.0f;
                o3 = yc + 10.0f;
                o4 = conf;
            }
        } else {
            // Pathological (<100 candidates): never hit with this data.
            o0 = o1 = o2 = o3 = o4 = 0.0f;
        }
        float* op = out + (size_t)b * (2 * MAXDET * 5) +
                    (is_player ? 0 : MAXDET * 5) + tid * 5;
        op[0] = o0; op[1] = o1; op[2] = o2; op[3] = o3; op[4] = o4;
    }
}

// ---------------------------------------------------------------------------

extern "C" void kernel_launch(void* const* d_in, const int* in_sizes, int n_in,
                              void* d_out, int out_size) {
    const float* pfm = nullptr;  // player feature map (64,2,68,120)
    const float* pbb = nullptr;  // player bbox        (64,4,68,120)
    const float* bfm = nullptr;  // ball feature map   (64,2,272,480)
    for (int i = 0; i < n_in; ++i) {
        if (in_sizes[i] == B_DIM * 2 * P_HW)      pfm = (const float*)d_in[i];
        else if (in_sizes[i] == B_DIM * 4 * P_HW) pbb = (const float*)d_in[i];
        else if (in_sizes[i] == B_DIM * 2 * B_HW) bfm = (const float*)d_in[i];
    }
    float* out = (float*)d_out;

    zero_cnt_kernel<<<1, 128>>>();
    nms_kernel<P_H, P_W, true ><<<dim3((P_W + 31) / 32, (P_H + 7) / 8, B_DIM),
                                  dim3(32, 8)>>>(pfm);
    nms_kernel<B_H, B_W, false><<<dim3(B_W / 32, B_H / 8, B_DIM),
                                  dim3(32, 8)>>>(bfm);
    select_kernel<<<2 * B_DIM, 1024>>>(pbb, out);
}